// round 13
// baseline (speedup 1.0000x reference)
#include <cuda_runtime.h>
#include <math.h>
#include <stdint.h>

#define BB 32
#define TT 4096
#define DD 1024
#define HH 16
#define DHH 64
#define FA 1.000244f
#define NSPLIT 16
#define TCH 16
#define MTS 1036

__device__ float g_chi[BB*DD*HH];
__device__ float g_sb[BB*HH];
__device__ float g_upart[NSPLIT*BB*HH*DD];
__device__ float g_spart[NSPLIT*BB*HH];
__device__ float g_ov[BB*DD];
__device__ float g_scores_s[BB*HH*TT];
__device__ float g_attn_s[BB*HH*TT];

__device__ __forceinline__ uint32_t f2tf(float x) {
    uint32_t u;
    asm("cvt.rna.tf32.f32 %0, %1;" : "=r"(u) : "f"(x));
    return u;
}
__device__ __forceinline__ void mma8(float* c, const uint32_t* a, const uint32_t* b) {
    asm("mma.sync.aligned.m16n8k8.row.col.f32.tf32.tf32.f32 "
        "{%0,%1,%2,%3},{%4,%5,%6,%7},{%8,%9},{%0,%1,%2,%3};"
        : "+f"(c[0]), "+f"(c[1]), "+f"(c[2]), "+f"(c[3])
        : "r"(a[0]), "r"(a[1]), "r"(a[2]), "r"(a[3]), "r"(b[0]), "r"(b[1]));
}
__device__ __forceinline__ void cpa16(float* dst, const float* src) {
    uint32_t d = (uint32_t)__cvta_generic_to_shared(dst);
    asm volatile("cp.async.cg.shared.global [%0], [%1], 16;" :: "r"(d), "l"(src));
}
#define CP_COMMIT() asm volatile("cp.async.commit_group;" ::: "memory")
#define CP_WAIT(n)  asm volatile("cp.async.wait_group %0;" :: "n"(n) : "memory")

// ---------------- K0: fused q-slice + c + sb, block per (h,b) ----------------
__global__ void __launch_bounds__(256) k_qc(const float* __restrict__ vector,
                                            const float* __restrict__ Wq,
                                            const float* __restrict__ bq,
                                            const float* __restrict__ Wk,
                                            const float* __restrict__ bk) {
    int h = blockIdx.x, b = blockIdx.y;
    int tid = threadIdx.x;
    __shared__ float vs[DD];
    __shared__ float qpart[4][64];
    __shared__ float qh[64];
    for (int i = tid; i < DD; i += 256) vs[i] = vector[b*DD + i];
    __syncthreads();
    int d = tid & 63, qq = tid >> 6;
    {
        float a[8] = {0.f,0.f,0.f,0.f,0.f,0.f,0.f,0.f};
        const float* wq = Wq + h*DHH + d;
        for (int i = qq*256; i < qq*256 + 256; i += 8) {
            #pragma unroll
            for (int j = 0; j < 8; j++)
                a[j] += vs[i+j] * wq[(size_t)(i+j)*DD];
        }
        qpart[qq][d] = ((a[0]+a[1])+(a[2]+a[3])) + ((a[4]+a[5])+(a[6]+a[7]));
    }
    __syncthreads();
    if (tid < 64) {
        float q = qpart[0][tid] + qpart[1][tid] + qpart[2][tid] + qpart[3][tid] + bq[h*DHH + tid];
        qh[tid] = q * 0.125f;
    }
    __syncthreads();
    if (tid == 0) {
        float s = 0.f;
        for (int dd = 0; dd < DHH; dd++) s += qh[dd] * bk[h*DHH + dd];
        g_sb[b*HH + h] = s;
    }
    for (int i = tid; i < DD; i += 256) {
        const float* w = Wk + (size_t)i*DD + h*DHH;
        float acc = 0.f;
        #pragma unroll
        for (int dd = 0; dd < DHH; dd += 4) {
            float4 wv = *(const float4*)(w + dd);
            acc += wv.x*qh[dd] + wv.y*qh[dd+1] + wv.z*qh[dd+2] + wv.w*qh[dd+3];
        }
        g_chi[((size_t)b*DD + i)*HH + h] = __uint_as_float(f2tf(acc * FA));
    }
}

// ---------------- fused: scores + exp + u — 512 threads, 16 warps ----------------
#define FU_MT (TCH*MTS)
#define FU_SMEM ((2*FU_MT + DD*HH + 16*272 + 320 + 32)*4)
__global__ void __launch_bounds__(512) k_fused(const float* __restrict__ matrix,
                                               const int* __restrict__ mask,
                                               float* __restrict__ scores,
                                               float* __restrict__ attn) {
    extern __shared__ float sm[];
    float* Mt   = sm;                 // 2 stages [16][MTS]
    float* Cs   = sm + 2*FU_MT;       // c hi [1024][16]
    float* Sred = Cs + DD*HH;         // [16 warps][272]
    float* Wsm  = Sred + 16*272;      // [16h][20]
    float* s_sm = Wsm + 320;
    float* s_sb = s_sm + 16;
    int ts = blockIdx.x, b = blockIdx.y;
    int tid = threadIdx.x, warp = tid >> 5, lane = tid & 31;
    int gid = lane >> 2, tig = lane & 3;
    int ib = warp * 64;               // this warp's 64-wide i-slice
    int et = tid & 15, eh = tid >> 4; // epilogue (t,h), valid for tid<256
    int tbeg = ts * 256;

    if (tid < 16) { s_sm[tid] = 0.f; s_sb[tid] = g_sb[b*16 + tid]; }

    {   // persist c tile
        const float* src = g_chi + (size_t)b*DD*HH;
        #pragma unroll
        for (int r = 0; r < 8; r++) {
            int f = (r*512 + tid) * 4;
            cpa16(&Cs[f], src + f);
        }
        CP_COMMIT();
    }
    const float* mbase = matrix + ((size_t)b*TT + tbeg)*DD;
    #define FU_ISSUE(ch, slot) do { \
        float* _m = Mt + (slot)*FU_MT; \
        const float* _g = mbase + (size_t)(ch)*TCH*DD; \
        _Pragma("unroll") \
        for (int r = 0; r < 8; r++) { \
            int f = r*512 + tid; int row = f >> 8; int c4 = (f & 255)*4; \
            cpa16(&_m[row*MTS + c4], _g + (size_t)row*DD + c4); } \
        CP_COMMIT(); \
    } while(0)

    FU_ISSUE(0, 0);
    FU_ISSUE(1, 1);

    float uacc[8][4];
    #pragma unroll
    for (int nt = 0; nt < 8; nt++)
        #pragma unroll
        for (int r = 0; r < 4; r++) uacc[nt][r] = 0.f;

    for (int c = 0; c < 16; c++) {
        if (c < 15) CP_WAIT(1); else CP_WAIT(0);
        __syncthreads();
        const float* mC = Mt + (c & 1)*FU_MT;
        int mk = (tid < 256) ? mask[b*TT + tbeg + c*TCH + et] : 0;

        // --- score mma: k over this warp's 64 i ---
        float sacc[2][4];
        #pragma unroll
        for (int nt = 0; nt < 2; nt++)
            #pragma unroll
            for (int r = 0; r < 4; r++) sacc[nt][r] = 0.f;
        #pragma unroll
        for (int ks = 0; ks < 8; ks++) {
            int kk = ks * 8;
            uint32_t ah[4];
            ah[0] = __float_as_uint(mC[(gid    )*MTS + ib + kk + tig]);
            ah[1] = __float_as_uint(mC[(gid + 8)*MTS + ib + kk + tig]);
            ah[2] = __float_as_uint(mC[(gid    )*MTS + ib + kk + tig + 4]);
            ah[3] = __float_as_uint(mC[(gid + 8)*MTS + ib + kk + tig + 4]);
            #pragma unroll
            for (int nt = 0; nt < 2; nt++) {
                uint32_t bh[2];
                bh[0] = __float_as_uint(Cs[(ib + kk + tig    )*16 + nt*8 + gid]);
                bh[1] = __float_as_uint(Cs[(ib + kk + tig + 4)*16 + nt*8 + gid]);
                mma8(sacc[nt], ah, bh);
            }
        }
        float* sr = Sred + warp*272;
        #pragma unroll
        for (int nt = 0; nt < 2; nt++) {
            int h = nt*8 + tig*2;
            sr[(gid    )*17 + h    ] = sacc[nt][0];
            sr[(gid    )*17 + h + 1] = sacc[nt][1];
            sr[(gid + 8)*17 + h    ] = sacc[nt][2];
            sr[(gid + 8)*17 + h + 1] = sacc[nt][3];
        }
        __syncthreads();

        // --- epilogue (first 8 warps): reduce 16 warps, exp, emit ---
        if (tid < 256) {
            float s = s_sb[eh];
            #pragma unroll
            for (int w = 0; w < 16; w++) s += Sred[w*272 + et*17 + eh];
            size_t oidx = ((size_t)b*HH + eh)*TT + tbeg + c*TCH + et;
            scores[oidx] = s;
            float e = (mk > 0) ? expf(s) : 0.f;
            attn[oidx] = e;
            float ss = e;
            #pragma unroll
            for (int o = 1; o < 16; o <<= 1) ss += __shfl_xor_sync(0xffffffffu, ss, o);
            if ((lane & 15) == 0) s_sm[eh] += ss;
            Wsm[eh*20 + et] = __uint_as_float(f2tf(e * FA));
        }
        __syncthreads();

        // --- u mma: D[16h][64i per warp], k = 16t ---
        #pragma unroll
        for (int ks = 0; ks < 2; ks++) {
            int kk = ks * 8;
            uint32_t ah[4];
            ah[0] = __float_as_uint(Wsm[(gid    )*20 + kk + tig]);
            ah[1] = __float_as_uint(Wsm[(gid + 8)*20 + kk + tig]);
            ah[2] = __float_as_uint(Wsm[(gid    )*20 + kk + tig + 4]);
            ah[3] = __float_as_uint(Wsm[(gid + 8)*20 + kk + tig + 4]);
            #pragma unroll
            for (int nt = 0; nt < 8; nt++) {
                uint32_t bh[2];
                bh[0] = __float_as_uint(mC[(kk + tig    )*MTS + ib + nt*8 + gid]);
                bh[1] = __float_as_uint(mC[(kk + tig + 4)*MTS + ib + nt*8 + gid]);
                mma8(uacc[nt], ah, bh);
            }
        }
        __syncthreads();
        if (c + 2 < 16) FU_ISSUE(c + 2, c & 1);
    }

    size_t base = ((size_t)(ts*BB + b))*HH*DD;
    #pragma unroll
    for (int nt = 0; nt < 8; nt++) {
        int i = ib + nt*8 + tig*2;
        *(float2*)&g_upart[base + (size_t)(gid    )*DD + i] = make_float2(uacc[nt][0], uacc[nt][1]);
        *(float2*)&g_upart[base + (size_t)(gid + 8)*DD + i] = make_float2(uacc[nt][2], uacc[nt][3]);
    }
    if (tid < 16) g_spart[(ts*BB + b)*HH + tid] = s_sm[tid];
}

// ---------------- ov: normalize attn row + (sum u partials) @ Wv + bv ----------
__global__ void __launch_bounds__(256) k_ov(const float* __restrict__ Wv,
                                            const float* __restrict__ bv,
                                            float* __restrict__ attn) {
    int h = blockIdx.x, b = blockIdx.y;
    int tid = threadIdx.x;
    __shared__ float us[DD];
    __shared__ float part[4][DHH];
    float sp = 0.f;
    #pragma unroll
    for (int t = 0; t < NSPLIT; t++) sp += g_spart[t*BB*HH + b*HH + h];
    float inv = 1.f / sp;
    // normalize this (b,h) attn row in place (independent of GEMV below)
    {
        float4* arow = (float4*)(attn + ((size_t)b*HH + h)*TT);
        #pragma unroll
        for (int r = 0; r < 4; r++) {
            float4 v = arow[r*256 + tid];
            v.x *= inv; v.y *= inv; v.z *= inv; v.w *= inv;
            arow[r*256 + tid] = v;
        }
    }
    // phase 1: reduce 16 partial slabs
    for (int i = tid; i < DD; i += 256) {
        float s = 0.f;
        #pragma unroll
        for (int ts = 0; ts < NSPLIT; ts++)
            s += g_upart[((size_t)(ts*BB + b)*HH + h)*DD + i];
        us[i] = s * inv;
    }
    __syncthreads();
    // phase 2: 4-way i-split dot products
    int d = tid & 63, q = tid >> 6;
    const float* w = Wv + h*DHH + d;
    float acc[8] = {0.f,0.f,0.f,0.f,0.f,0.f,0.f,0.f};
    int i0 = q * 256;
    #pragma unroll 4
    for (int i = i0; i < i0 + 256; i += 8) {
        #pragma unroll
        for (int j = 0; j < 8; j++)
            acc[j] += us[i+j] * w[(size_t)(i+j)*DD];
    }
    part[q][d] = ((acc[0]+acc[1])+(acc[2]+acc[3])) + ((acc[4]+acc[5])+(acc[6]+acc[7]));
    __syncthreads();
    if (tid < 64)
        g_ov[b*DD + h*DHH + tid] =
            part[0][tid] + part[1][tid] + part[2][tid] + part[3][tid] + bv[h*DHH + tid];
}

// ---------------- out = ov @ Wo + bo ----------------
__global__ void __launch_bounds__(1024) k_out(const float* __restrict__ Wo,
                                              const float* __restrict__ bo,
                                              float* __restrict__ out) {
    int b = blockIdx.y;
    int ol = threadIdx.x & 255, q = threadIdx.x >> 8;
    int o = blockIdx.x*256 + ol;
    __shared__ float vs[DD];
    __shared__ float part[3][256];
    for (int i = threadIdx.x; i < DD; i += 1024) vs[i] = g_ov[b*DD + i];
    __syncthreads();
    float acc[8] = {0.f,0.f,0.f,0.f,0.f,0.f,0.f,0.f};
    int j0 = q * 256;
    #pragma unroll 4
    for (int j = j0; j < j0 + 256; j += 8) {
        #pragma unroll
        for (int r = 0; r < 8; r++)
            acc[r] += vs[j+r] * Wo[(size_t)(j+r)*DD + o];
    }
    float p = ((acc[0]+acc[1])+(acc[2]+acc[3])) + ((acc[4]+acc[5])+(acc[6]+acc[7]));
    if (q) part[q-1][ol] = p;
    __syncthreads();
    if (q == 0)
        out[b*DD + o] = p + part[0][ol] + part[1][ol] + part[2][ol] + bo[o];
}

// ---------------- host launcher (4 launches) ----------------
extern "C" void kernel_launch(void* const* d_in, const int* in_sizes, int n_in,
                              void* d_out, int out_size) {
    const float* vector = (const float*)d_in[0];
    const float* matrix = (const float*)d_in[1];
    const int*   mask   = (const int*)  d_in[2];
    const float* Wq     = (const float*)d_in[3];
    const float* bq     = (const float*)d_in[4];
    const float* Wk     = (const float*)d_in[5];
    const float* bk     = (const float*)d_in[6];
    const float* Wv     = (const float*)d_in[7];
    const float* bv     = (const float*)d_in[8];
    const float* Wo     = (const float*)d_in[9];
    const float* bo     = (const float*)d_in[10];

    float* out = (float*)d_out;
    const int FULL = BB*DD + 2*BB*HH*TT;
    float *attn, *scores;
    if (out_size >= FULL) {
        attn   = out + BB*DD;
        scores = attn + (size_t)BB*HH*TT;
    } else {
        void* p;
        cudaGetSymbolAddress(&p, g_scores_s); scores = (float*)p;
        cudaGetSymbolAddress(&p, g_attn_s);   attn   = (float*)p;
    }

    cudaFuncSetAttribute(k_fused, cudaFuncAttributeMaxDynamicSharedMemorySize, FU_SMEM);

    k_qc   <<<dim3(HH, BB),       256>>>(vector, Wq, bq, Wk, bk);
    k_fused<<<dim3(NSPLIT, BB),   512, FU_SMEM>>>(matrix, mask, scores, attn);
    k_ov   <<<dim3(HH, BB),       256>>>(Wv, bv, attn);
    k_out  <<<dim3(4, BB),       1024>>>(Wo, bo, out);
}

// round 14
// speedup vs baseline: 1.1745x; 1.1745x over previous
#include <cuda_runtime.h>
#include <math.h>
#include <stdint.h>

#define BB 32
#define TT 4096
#define DD 1024
#define HH 16
#define DHH 64
#define FA 1.000244f
#define NSPLIT 16
#define TCH 16
#define MTS 1036

__device__ float g_chi[BB*DD*HH];
__device__ float g_sb[BB*HH];
__device__ float g_upart[NSPLIT*BB*HH*DD];
__device__ float g_spart[NSPLIT*BB*HH];
__device__ float g_ov[BB*DD];
__device__ float g_scores_s[BB*HH*TT];
__device__ float g_attn_s[BB*HH*TT];

__device__ __forceinline__ uint32_t f2tf(float x) {
    uint32_t u;
    asm("cvt.rna.tf32.f32 %0, %1;" : "=r"(u) : "f"(x));
    return u;
}
__device__ __forceinline__ void mma8(float* c, const uint32_t* a, const uint32_t* b) {
    asm("mma.sync.aligned.m16n8k8.row.col.f32.tf32.tf32.f32 "
        "{%0,%1,%2,%3},{%4,%5,%6,%7},{%8,%9},{%0,%1,%2,%3};"
        : "+f"(c[0]), "+f"(c[1]), "+f"(c[2]), "+f"(c[3])
        : "r"(a[0]), "r"(a[1]), "r"(a[2]), "r"(a[3]), "r"(b[0]), "r"(b[1]));
}
__device__ __forceinline__ void cpa16(float* dst, const float* src) {
    uint32_t d = (uint32_t)__cvta_generic_to_shared(dst);
    asm volatile("cp.async.cg.shared.global [%0], [%1], 16;" :: "r"(d), "l"(src));
}
#define CP_COMMIT() asm volatile("cp.async.commit_group;" ::: "memory")
#define CP_WAIT(n)  asm volatile("cp.async.wait_group %0;" :: "n"(n) : "memory")

// ---------------- K0: fused q-slice + c + sb, block per (h,b) ----------------
__global__ void __launch_bounds__(256) k_qc(const float* __restrict__ vector,
                                            const float* __restrict__ Wq,
                                            const float* __restrict__ bq,
                                            const float* __restrict__ Wk,
                                            const float* __restrict__ bk) {
    int h = blockIdx.x, b = blockIdx.y;
    int tid = threadIdx.x;
    __shared__ float vs[DD];
    __shared__ float qpart[4][64];
    __shared__ float qh[64];
    for (int i = tid; i < DD; i += 256) vs[i] = vector[b*DD + i];
    __syncthreads();
    int d = tid & 63, qq = tid >> 6;
    {
        float a[8] = {0.f,0.f,0.f,0.f,0.f,0.f,0.f,0.f};
        const float* wq = Wq + h*DHH + d;
        for (int i = qq*256; i < qq*256 + 256; i += 8) {
            #pragma unroll
            for (int j = 0; j < 8; j++)
                a[j] += vs[i+j] * wq[(size_t)(i+j)*DD];
        }
        qpart[qq][d] = ((a[0]+a[1])+(a[2]+a[3])) + ((a[4]+a[5])+(a[6]+a[7]));
    }
    __syncthreads();
    if (tid < 64) {
        float q = qpart[0][tid] + qpart[1][tid] + qpart[2][tid] + qpart[3][tid] + bq[h*DHH + tid];
        qh[tid] = q * 0.125f;
    }
    __syncthreads();
    if (tid == 0) {
        float s = 0.f;
        for (int dd = 0; dd < DHH; dd++) s += qh[dd] * bk[h*DHH + dd];
        g_sb[b*HH + h] = s;
    }
    for (int i = tid; i < DD; i += 256) {
        const float* w = Wk + (size_t)i*DD + h*DHH;
        float acc = 0.f;
        #pragma unroll
        for (int dd = 0; dd < DHH; dd += 4) {
            float4 wv = *(const float4*)(w + dd);
            acc += wv.x*qh[dd] + wv.y*qh[dd+1] + wv.z*qh[dd+2] + wv.w*qh[dd+3];
        }
        g_chi[((size_t)b*DD + i)*HH + h] = __uint_as_float(f2tf(acc * FA));
    }
}

// ---------------- fused: scores + exp + u — 256 threads (R11 config) ----------------
#define FU_MT (TCH*MTS)
#define FU_SMEM ((2*FU_MT + DD*HH + 8*272 + 320 + 32)*4)
__global__ void __launch_bounds__(256) k_fused(const float* __restrict__ matrix,
                                               const int* __restrict__ mask,
                                               float* __restrict__ scores,
                                               float* __restrict__ attn) {
    extern __shared__ float sm[];
    float* Mt   = sm;
    float* Cs   = sm + 2*FU_MT;
    float* Sred = Cs + DD*HH;
    float* Wsm  = Sred + 8*272;
    float* s_sm = Wsm + 320;
    float* s_sb = s_sm + 16;
    int ts = blockIdx.x, b = blockIdx.y;
    int tid = threadIdx.x, warp = tid >> 5, lane = tid & 31;
    int gid = lane >> 2, tig = lane & 3;
    int ib = warp * 128;
    int et = tid & 15, eh = tid >> 4;
    int tbeg = ts * 256;

    if (tid < 16) { s_sm[tid] = 0.f; s_sb[tid] = g_sb[b*16 + tid]; }

    {
        const float* src = g_chi + (size_t)b*DD*HH;
        #pragma unroll
        for (int r = 0; r < 16; r++) {
            int f = (r*256 + tid) * 4;
            cpa16(&Cs[f], src + f);
        }
        CP_COMMIT();
    }
    const float* mbase = matrix + ((size_t)b*TT + tbeg)*DD;
    #define FU_ISSUE(ch, slot) do { \
        float* _m = Mt + (slot)*FU_MT; \
        const float* _g = mbase + (size_t)(ch)*TCH*DD; \
        _Pragma("unroll") \
        for (int r = 0; r < 16; r++) { \
            int f = r*256 + tid; int row = f >> 8; int c4 = (f & 255)*4; \
            cpa16(&_m[row*MTS + c4], _g + (size_t)row*DD + c4); } \
        CP_COMMIT(); \
    } while(0)

    FU_ISSUE(0, 0);
    FU_ISSUE(1, 1);

    float uacc[16][4];
    #pragma unroll
    for (int nt = 0; nt < 16; nt++)
        #pragma unroll
        for (int r = 0; r < 4; r++) uacc[nt][r] = 0.f;

    for (int c = 0; c < 16; c++) {
        if (c < 15) CP_WAIT(1); else CP_WAIT(0);
        __syncthreads();
        const float* mC = Mt + (c & 1)*FU_MT;
        int mk = mask[b*TT + tbeg + c*TCH + et];

        float sacc[2][4];
        #pragma unroll
        for (int nt = 0; nt < 2; nt++)
            #pragma unroll
            for (int r = 0; r < 4; r++) sacc[nt][r] = 0.f;
        #pragma unroll
        for (int ks = 0; ks < 16; ks++) {
            int kk = ks * 8;
            uint32_t ah[4];
            ah[0] = __float_as_uint(mC[(gid    )*MTS + ib + kk + tig]);
            ah[1] = __float_as_uint(mC[(gid + 8)*MTS + ib + kk + tig]);
            ah[2] = __float_as_uint(mC[(gid    )*MTS + ib + kk + tig + 4]);
            ah[3] = __float_as_uint(mC[(gid + 8)*MTS + ib + kk + tig + 4]);
            #pragma unroll
            for (int nt = 0; nt < 2; nt++) {
                uint32_t bh[2];
                bh[0] = __float_as_uint(Cs[(ib + kk + tig    )*16 + nt*8 + gid]);
                bh[1] = __float_as_uint(Cs[(ib + kk + tig + 4)*16 + nt*8 + gid]);
                mma8(sacc[nt], ah, bh);
            }
        }
        float* sr = Sred + warp*272;
        #pragma unroll
        for (int nt = 0; nt < 2; nt++) {
            int h = nt*8 + tig*2;
            sr[(gid    )*17 + h    ] = sacc[nt][0];
            sr[(gid    )*17 + h + 1] = sacc[nt][1];
            sr[(gid + 8)*17 + h    ] = sacc[nt][2];
            sr[(gid + 8)*17 + h + 1] = sacc[nt][3];
        }
        __syncthreads();

        {
            float s = s_sb[eh];
            #pragma unroll
            for (int w = 0; w < 8; w++) s += Sred[w*272 + et*17 + eh];
            size_t oidx = ((size_t)b*HH + eh)*TT + tbeg + c*TCH + et;
            scores[oidx] = s;
            float e = (mk > 0) ? expf(s) : 0.f;
            attn[oidx] = e;
            float ss = e;
            #pragma unroll
            for (int o = 1; o < 16; o <<= 1) ss += __shfl_xor_sync(0xffffffffu, ss, o);
            if ((lane & 15) == 0) s_sm[eh] += ss;
            Wsm[eh*20 + et] = __uint_as_float(f2tf(e * FA));
        }
        __syncthreads();

        #pragma unroll
        for (int ks = 0; ks < 2; ks++) {
            int kk = ks * 8;
            uint32_t ah[4];
            ah[0] = __float_as_uint(Wsm[(gid    )*20 + kk + tig]);
            ah[1] = __float_as_uint(Wsm[(gid + 8)*20 + kk + tig]);
            ah[2] = __float_as_uint(Wsm[(gid    )*20 + kk + tig + 4]);
            ah[3] = __float_as_uint(Wsm[(gid + 8)*20 + kk + tig + 4]);
            #pragma unroll
            for (int nt = 0; nt < 16; nt++) {
                uint32_t bh[2];
                bh[0] = __float_as_uint(mC[(kk + tig    )*MTS + ib + nt*8 + gid]);
                bh[1] = __float_as_uint(mC[(kk + tig + 4)*MTS + ib + nt*8 + gid]);
                mma8(uacc[nt], ah, bh);
            }
        }
        __syncthreads();
        if (c + 2 < 16) FU_ISSUE(c + 2, c & 1);
    }

    size_t base = ((size_t)(ts*BB + b))*HH*DD;
    #pragma unroll
    for (int nt = 0; nt < 16; nt++) {
        int i = ib + nt*8 + tig*2;
        *(float2*)&g_upart[base + (size_t)(gid    )*DD + i] = make_float2(uacc[nt][0], uacc[nt][1]);
        *(float2*)&g_upart[base + (size_t)(gid + 8)*DD + i] = make_float2(uacc[nt][2], uacc[nt][3]);
    }
    if (tid < 16) g_spart[(ts*BB + b)*HH + tid] = s_sm[tid];
}

// ---------------- ov: normalize attn row + (sum u partials) @ Wv + bv ----------
__global__ void __launch_bounds__(256) k_ov(const float* __restrict__ Wv,
                                            const float* __restrict__ bv,
                                            float* __restrict__ attn) {
    int h = blockIdx.x, b = blockIdx.y;
    int tid = threadIdx.x;
    __shared__ float us[DD];
    __shared__ float part[4][DHH];
    float sp = 0.f;
    #pragma unroll
    for (int t = 0; t < NSPLIT; t++) sp += g_spart[t*BB*HH + b*HH + h];
    float inv = 1.f / sp;
    {
        float4* arow = (float4*)(attn + ((size_t)b*HH + h)*TT);
        #pragma unroll
        for (int r = 0; r < 4; r++) {
            float4 v = arow[r*256 + tid];
            v.x *= inv; v.y *= inv; v.z *= inv; v.w *= inv;
            arow[r*256 + tid] = v;
        }
    }
    for (int i = tid; i < DD; i += 256) {
        float s = 0.f;
        #pragma unroll
        for (int ts = 0; ts < NSPLIT; ts++)
            s += g_upart[((size_t)(ts*BB + b)*HH + h)*DD + i];
        us[i] = s * inv;
    }
    __syncthreads();
    int d = tid & 63, q = tid >> 6;
    const float* w = Wv + h*DHH + d;
    float acc[8] = {0.f,0.f,0.f,0.f,0.f,0.f,0.f,0.f};
    int i0 = q * 256;
    #pragma unroll 4
    for (int i = i0; i < i0 + 256; i += 8) {
        #pragma unroll
        for (int j = 0; j < 8; j++)
            acc[j] += us[i+j] * w[(size_t)(i+j)*DD];
    }
    part[q][d] = ((acc[0]+acc[1])+(acc[2]+acc[3])) + ((acc[4]+acc[5])+(acc[6]+acc[7]));
    __syncthreads();
    if (tid < 64)
        g_ov[b*DD + h*DHH + tid] =
            part[0][tid] + part[1][tid] + part[2][tid] + part[3][tid] + bv[h*DHH + tid];
}

// ---------------- out = ov @ Wo + bo (16-deep ILP per thread) ----------------
__global__ void __launch_bounds__(1024) k_out(const float* __restrict__ Wo,
                                              const float* __restrict__ bo,
                                              float* __restrict__ out) {
    int b = blockIdx.y;
    int ol = threadIdx.x & 255, q = threadIdx.x >> 8;
    int o = blockIdx.x*256 + ol;
    __shared__ float vs[DD];
    __shared__ float part[3][256];
    for (int i = threadIdx.x; i < DD; i += 1024) vs[i] = g_ov[b*DD + i];
    __syncthreads();
    float acc[16];
    #pragma unroll
    for (int r = 0; r < 16; r++) acc[r] = 0.f;
    int j0 = q * 256;
    #pragma unroll 2
    for (int j = j0; j < j0 + 256; j += 16) {
        #pragma unroll
        for (int r = 0; r < 16; r++)
            acc[r] += vs[j+r] * Wo[(size_t)(j+r)*DD + o];
    }
    float p = 0.f;
    #pragma unroll
    for (int r = 0; r < 16; r++) p += acc[r];
    if (q) part[q-1][ol] = p;
    __syncthreads();
    if (q == 0)
        out[b*DD + o] = p + part[0][ol] + part[1][ol] + part[2][ol] + bo[o];
}

// ---------------- host launcher (4 launches) ----------------
extern "C" void kernel_launch(void* const* d_in, const int* in_sizes, int n_in,
                              void* d_out, int out_size) {
    const float* vector = (const float*)d_in[0];
    const float* matrix = (const float*)d_in[1];
    const int*   mask   = (const int*)  d_in[2];
    const float* Wq     = (const float*)d_in[3];
    const float* bq     = (const float*)d_in[4];
    const float* Wk     = (const float*)d_in[5];
    const float* bk     = (const float*)d_in[6];
    const float* Wv     = (const float*)d_in[7];
    const float* bv     = (const float*)d_in[8];
    const float* Wo     = (const float*)d_in[9];
    const float* bo     = (const float*)d_in[10];

    float* out = (float*)d_out;
    const int FULL = BB*DD + 2*BB*HH*TT;
    float *attn, *scores;
    if (out_size >= FULL) {
        attn   = out + BB*DD;
        scores = attn + (size_t)BB*HH*TT;
    } else {
        void* p;
        cudaGetSymbolAddress(&p, g_scores_s); scores = (float*)p;
        cudaGetSymbolAddress(&p, g_attn_s);   attn   = (float*)p;
    }

    cudaFuncSetAttribute(k_fused, cudaFuncAttributeMaxDynamicSharedMemorySize, FU_SMEM);

    k_qc   <<<dim3(HH, BB),       256>>>(vector, Wq, bq, Wk, bk);
    k_fused<<<dim3(NSPLIT, BB),   256, FU_SMEM>>>(matrix, mask, scores, attn);
    k_ov   <<<dim3(HH, BB),       256>>>(Wv, bv, attn);
    k_out  <<<dim3(4, BB),       1024>>>(Wo, bo, out);
}

// round 15
// speedup vs baseline: 1.2360x; 1.0524x over previous
#include <cuda_runtime.h>
#include <math.h>
#include <stdint.h>

#define BB 32
#define TT 4096
#define DD 1024
#define HH 16
#define DHH 64
#define FA 1.000244f
#define NSPLIT 4
#define TCH 16
#define MTS 1036

__device__ float g_chi[BB*DD*HH];
__device__ float g_sb[BB*HH];
__device__ float g_upart[NSPLIT*BB*HH*DD];
__device__ float g_spart[NSPLIT*BB*HH];
__device__ float g_ov[BB*DD];
__device__ float g_scores_s[BB*HH*TT];
__device__ float g_attn_s[BB*HH*TT];

__device__ __forceinline__ uint32_t f2tf(float x) {
    uint32_t u;
    asm("cvt.rna.tf32.f32 %0, %1;" : "=r"(u) : "f"(x));
    return u;
}
__device__ __forceinline__ void mma8(float* c, const uint32_t* a, const uint32_t* b) {
    asm("mma.sync.aligned.m16n8k8.row.col.f32.tf32.tf32.f32 "
        "{%0,%1,%2,%3},{%4,%5,%6,%7},{%8,%9},{%0,%1,%2,%3};"
        : "+f"(c[0]), "+f"(c[1]), "+f"(c[2]), "+f"(c[3])
        : "r"(a[0]), "r"(a[1]), "r"(a[2]), "r"(a[3]), "r"(b[0]), "r"(b[1]));
}
__device__ __forceinline__ void cpa16(float* dst, const float* src) {
    uint32_t d = (uint32_t)__cvta_generic_to_shared(dst);
    asm volatile("cp.async.cg.shared.global [%0], [%1], 16;" :: "r"(d), "l"(src));
}
#define CP_COMMIT() asm volatile("cp.async.commit_group;" ::: "memory")
#define CP_WAIT(n)  asm volatile("cp.async.wait_group %0;" :: "n"(n) : "memory")

// ---------------- K0: fused q-slice + c + sb, block per (h,b) ----------------
__global__ void __launch_bounds__(256) k_qc(const float* __restrict__ vector,
                                            const float* __restrict__ Wq,
                                            const float* __restrict__ bq,
                                            const float* __restrict__ Wk,
                                            const float* __restrict__ bk) {
    int h = blockIdx.x, b = blockIdx.y;
    int tid = threadIdx.x;
    __shared__ float vs[DD];
    __shared__ float qpart[4][64];
    __shared__ float qh[64];
    for (int i = tid; i < DD; i += 256) vs[i] = vector[b*DD + i];
    __syncthreads();
    int d = tid & 63, qq = tid >> 6;
    {
        float a[8] = {0.f,0.f,0.f,0.f,0.f,0.f,0.f,0.f};
        const float* wq = Wq + h*DHH + d;
        for (int i = qq*256; i < qq*256 + 256; i += 8) {
            #pragma unroll
            for (int j = 0; j < 8; j++)
                a[j] += vs[i+j] * wq[(size_t)(i+j)*DD];
        }
        qpart[qq][d] = ((a[0]+a[1])+(a[2]+a[3])) + ((a[4]+a[5])+(a[6]+a[7]));
    }
    __syncthreads();
    if (tid < 64) {
        float q = qpart[0][tid] + qpart[1][tid] + qpart[2][tid] + qpart[3][tid] + bq[h*DHH + tid];
        qh[tid] = q * 0.125f;
    }
    __syncthreads();
    if (tid == 0) {
        float s = 0.f;
        for (int dd = 0; dd < DHH; dd++) s += qh[dd] * bk[h*DHH + dd];
        g_sb[b*HH + h] = s;
    }
    // c: 2-way i-unroll for L2 MLP
    for (int i = tid; i < DD; i += 512) {
        const float* w0 = Wk + (size_t)i*DD + h*DHH;
        const float* w1 = Wk + (size_t)(i+256)*DD + h*DHH;
        float a0 = 0.f, a1 = 0.f;
        #pragma unroll
        for (int dd = 0; dd < DHH; dd += 4) {
            float4 v0 = *(const float4*)(w0 + dd);
            float4 v1 = *(const float4*)(w1 + dd);
            a0 += v0.x*qh[dd] + v0.y*qh[dd+1] + v0.z*qh[dd+2] + v0.w*qh[dd+3];
            a1 += v1.x*qh[dd] + v1.y*qh[dd+1] + v1.z*qh[dd+2] + v1.w*qh[dd+3];
        }
        g_chi[((size_t)b*DD + i)*HH + h]       = __uint_as_float(f2tf(a0 * FA));
        g_chi[((size_t)b*DD + i + 256)*HH + h] = __uint_as_float(f2tf(a1 * FA));
    }
}

// ---------------- fused: scores + exp + u — 256 threads ----------------
// Cs layout: split halves — CsA: h 0-7 at [i*8+h], CsB: h 8-15 at 8192 + [i*8+h]
#define FU_MT (TCH*MTS)
#define FU_SMEM ((2*FU_MT + DD*HH + 8*272 + 320 + 32)*4)
__global__ void __launch_bounds__(256) k_fused(const float* __restrict__ matrix,
                                               const int* __restrict__ mask,
                                               float* __restrict__ scores,
                                               float* __restrict__ attn) {
    extern __shared__ float sm[];
    float* Mt   = sm;
    float* Cs   = sm + 2*FU_MT;       // 16384 floats, split-half layout
    float* Sred = Cs + DD*HH;
    float* Wsm  = Sred + 8*272;
    float* s_sm = Wsm + 320;
    float* s_sb = s_sm + 16;
    int ts = blockIdx.x, b = blockIdx.y;
    int tid = threadIdx.x, warp = tid >> 5, lane = tid & 31;
    int gid = lane >> 2, tig = lane & 3;
    int ib = warp * 128;
    int et = tid & 15, eh = tid >> 4;
    int tbeg = ts * 1024;

    if (tid < 16) { s_sm[tid] = 0.f; s_sb[tid] = g_sb[b*16 + tid]; }

    {   // persist c tile into split-half layout
        const float* src = g_chi + (size_t)b*DD*HH;
        #pragma unroll
        for (int r = 0; r < 16; r++) {
            int f  = (r*256 + tid) * 4;           // linear float4 offset in g_chi
            int i  = f >> 4;                      // i row
            int h4 = f & 15;                      // 0,4,8,12
            int dst = (h4 & 8) ? (8192 + i*8 + (h4 & 7)) : (i*8 + h4);
            cpa16(&Cs[dst], src + f);
        }
        CP_COMMIT();
    }
    const float* mbase = matrix + ((size_t)b*TT + tbeg)*DD;
    #define FU_ISSUE(ch, slot) do { \
        float* _m = Mt + (slot)*FU_MT; \
        const float* _g = mbase + (size_t)(ch)*TCH*DD; \
        _Pragma("unroll") \
        for (int r = 0; r < 16; r++) { \
            int f = r*256 + tid; int row = f >> 8; int c4 = (f & 255)*4; \
            cpa16(&_m[row*MTS + c4], _g + (size_t)row*DD + c4); } \
        CP_COMMIT(); \
    } while(0)

    FU_ISSUE(0, 0);
    FU_ISSUE(1, 1);

    float uacc[16][4];
    #pragma unroll
    for (int nt = 0; nt < 16; nt++)
        #pragma unroll
        for (int r = 0; r < 4; r++) uacc[nt][r] = 0.f;

    for (int c = 0; c < 64; c++) {
        if (c < 63) CP_WAIT(1); else CP_WAIT(0);
        __syncthreads();
        const float* mC = Mt + (c & 1)*FU_MT;
        int mk = mask[b*TT + tbeg + c*TCH + et];

        float sacc[2][4];
        #pragma unroll
        for (int nt = 0; nt < 2; nt++)
            #pragma unroll
            for (int r = 0; r < 4; r++) sacc[nt][r] = 0.f;
        #pragma unroll
        for (int ks = 0; ks < 16; ks++) {
            int kk = ks * 8;
            uint32_t ah[4];
            ah[0] = __float_as_uint(mC[(gid    )*MTS + ib + kk + tig]);
            ah[1] = __float_as_uint(mC[(gid + 8)*MTS + ib + kk + tig]);
            ah[2] = __float_as_uint(mC[(gid    )*MTS + ib + kk + tig + 4]);
            ah[3] = __float_as_uint(mC[(gid + 8)*MTS + ib + kk + tig + 4]);
            #pragma unroll
            for (int nt = 0; nt < 2; nt++) {
                uint32_t bh[2];
                bh[0] = __float_as_uint(Cs[nt*8192 + (ib + kk + tig    )*8 + gid]);
                bh[1] = __float_as_uint(Cs[nt*8192 + (ib + kk + tig + 4)*8 + gid]);
                mma8(sacc[nt], ah, bh);
            }
        }
        float* sr = Sred + warp*272;
        #pragma unroll
        for (int nt = 0; nt < 2; nt++) {
            int h = nt*8 + tig*2;
            sr[(gid    )*17 + h    ] = sacc[nt][0];
            sr[(gid    )*17 + h + 1] = sacc[nt][1];
            sr[(gid + 8)*17 + h    ] = sacc[nt][2];
            sr[(gid + 8)*17 + h + 1] = sacc[nt][3];
        }
        __syncthreads();

        {
            float s = s_sb[eh];
            #pragma unroll
            for (int w = 0; w < 8; w++) s += Sred[w*272 + et*17 + eh];
            size_t oidx = ((size_t)b*HH + eh)*TT + tbeg + c*TCH + et;
            scores[oidx] = s;
            float e = (mk > 0) ? expf(s) : 0.f;
            attn[oidx] = e;
            float ss = e;
            #pragma unroll
            for (int o = 1; o < 16; o <<= 1) ss += __shfl_xor_sync(0xffffffffu, ss, o);
            if ((lane & 15) == 0) s_sm[eh] += ss;
            Wsm[eh*20 + et] = __uint_as_float(f2tf(e * FA));
        }
        __syncthreads();

        #pragma unroll
        for (int ks = 0; ks < 2; ks++) {
            int kk = ks * 8;
            uint32_t ah[4];
            ah[0] = __float_as_uint(Wsm[(gid    )*20 + kk + tig]);
            ah[1] = __float_as_uint(Wsm[(gid + 8)*20 + kk + tig]);
            ah[2] = __float_as_uint(Wsm[(gid    )*20 + kk + tig + 4]);
            ah[3] = __float_as_uint(Wsm[(gid + 8)*20 + kk + tig + 4]);
            #pragma unroll
            for (int nt = 0; nt < 16; nt++) {
                uint32_t bh[2];
                bh[0] = __float_as_uint(mC[(kk + tig    )*MTS + ib + nt*8 + gid]);
                bh[1] = __float_as_uint(mC[(kk + tig + 4)*MTS + ib + nt*8 + gid]);
                mma8(uacc[nt], ah, bh);
            }
        }
        __syncthreads();
        if (c + 2 < 64) FU_ISSUE(c + 2, c & 1);
    }

    size_t base = ((size_t)(ts*BB + b))*HH*DD;
    #pragma unroll
    for (int nt = 0; nt < 16; nt++) {
        int i = ib + nt*8 + tig*2;
        *(float2*)&g_upart[base + (size_t)(gid    )*DD + i] = make_float2(uacc[nt][0], uacc[nt][1]);
        *(float2*)&g_upart[base + (size_t)(gid + 8)*DD + i] = make_float2(uacc[nt][2], uacc[nt][3]);
    }
    if (tid < 16) g_spart[(ts*BB + b)*HH + tid] = s_sm[tid];
}

// ---------------- ov: normalize attn row + (sum u partials) @ Wv + bv ----------
__global__ void __launch_bounds__(256) k_ov(const float* __restrict__ Wv,
                                            const float* __restrict__ bv,
                                            float* __restrict__ attn) {
    int h = blockIdx.x, b = blockIdx.y;
    int tid = threadIdx.x;
    __shared__ float us[DD];
    __shared__ float part[4][DHH];
    float sp = 0.f;
    #pragma unroll
    for (int t = 0; t < NSPLIT; t++) sp += g_spart[t*BB*HH + b*HH + h];
    float inv = 1.f / sp;
    {
        float4* arow = (float4*)(attn + ((size_t)b*HH + h)*TT);
        #pragma unroll
        for (int r = 0; r < 4; r++) {
            float4 v = arow[r*256 + tid];
            v.x *= inv; v.y *= inv; v.z *= inv; v.w *= inv;
            arow[r*256 + tid] = v;
        }
    }
    for (int i = tid; i < DD; i += 256) {
        float s = 0.f;
        #pragma unroll
        for (int ts = 0; ts < NSPLIT; ts++)
            s += g_upart[((size_t)(ts*BB + b)*HH + h)*DD + i];
        us[i] = s * inv;
    }
    __syncthreads();
    int d = tid & 63, q = tid >> 6;
    const float* w = Wv + h*DHH + d;
    float acc[8] = {0.f,0.f,0.f,0.f,0.f,0.f,0.f,0.f};
    int i0 = q * 256;
    #pragma unroll 4
    for (int i = i0; i < i0 + 256; i += 8) {
        #pragma unroll
        for (int j = 0; j < 8; j++)
            acc[j] += us[i+j] * w[(size_t)(i+j)*DD];
    }
    part[q][d] = ((acc[0]+acc[1])+(acc[2]+acc[3])) + ((acc[4]+acc[5])+(acc[6]+acc[7]));
    __syncthreads();
    if (tid < 64)
        g_ov[b*DD + h*DHH + tid] =
            part[0][tid] + part[1][tid] + part[2][tid] + part[3][tid] + bv[h*DHH + tid];
}

// ---------------- out = ov @ Wo + bo ----------------
__global__ void __launch_bounds__(1024) k_out(const float* __restrict__ Wo,
                                              const float* __restrict__ bo,
                                              float* __restrict__ out) {
    int b = blockIdx.y;
    int ol = threadIdx.x & 255, q = threadIdx.x >> 8;
    int o = blockIdx.x*256 + ol;
    __shared__ float vs[DD];
    __shared__ float part[3][256];
    for (int i = threadIdx.x; i < DD; i += 1024) vs[i] = g_ov[b*DD + i];
    __syncthreads();
    float acc[16];
    #pragma unroll
    for (int r = 0; r < 16; r++) acc[r] = 0.f;
    int j0 = q * 256;
    #pragma unroll 2
    for (int j = j0; j < j0 + 256; j += 16) {
        #pragma unroll
        for (int r = 0; r < 16; r++)
            acc[r] += vs[j+r] * Wo[(size_t)(j+r)*DD + o];
    }
    float p = 0.f;
    #pragma unroll
    for (int r = 0; r < 16; r++) p += acc[r];
    if (q) part[q-1][ol] = p;
    __syncthreads();
    if (q == 0)
        out[b*DD + o] = p + part[0][ol] + part[1][ol] + part[2][ol] + bo[o];
}

// ---------------- host launcher (4 launches) ----------------
extern "C" void kernel_launch(void* const* d_in, const int* in_sizes, int n_in,
                              void* d_out, int out_size) {
    const float* vector = (const float*)d_in[0];
    const float* matrix = (const float*)d_in[1];
    const int*   mask   = (const int*)  d_in[2];
    const float* Wq     = (const float*)d_in[3];
    const float* bq     = (const float*)d_in[4];
    const float* Wk     = (const float*)d_in[5];
    const float* bk     = (const float*)d_in[6];
    const float* Wv     = (const float*)d_in[7];
    const float* bv     = (const float*)d_in[8];
    const float* Wo     = (const float*)d_in[9];
    const float* bo     = (const float*)d_in[10];

    float* out = (float*)d_out;
    const int FULL = BB*DD + 2*BB*HH*TT;
    float *attn, *scores;
    if (out_size >= FULL) {
        attn   = out + BB*DD;
        scores = attn + (size_t)BB*HH*TT;
    } else {
        void* p;
        cudaGetSymbolAddress(&p, g_scores_s); scores = (float*)p;
        cudaGetSymbolAddress(&p, g_attn_s);   attn   = (float*)p;
    }

    cudaFuncSetAttribute(k_fused, cudaFuncAttributeMaxDynamicSharedMemorySize, FU_SMEM);

    k_qc   <<<dim3(HH, BB),       256>>>(vector, Wq, bq, Wk, bk);
    k_fused<<<dim3(NSPLIT, BB),   256, FU_SMEM>>>(matrix, mask, scores, attn);
    k_ov   <<<dim3(HH, BB),       256>>>(Wv, bv, attn);
    k_out  <<<dim3(4, BB),       1024>>>(Wo, bo, out);
}